// round 7
// baseline (speedup 1.0000x reference)
#include <cuda_runtime.h>

#define B_  128
#define N_  4096
#define K_  100
#define P_  4096
#define T_  1024          // threads per block
#define NB_ 512           // LUT buckets

// Device globals (no allocation in kernel_launch, per harness rules)
__device__ double g_loss[B_];
__device__ int    g_flag[B_];    // zero-init; block 0 resets after consuming

#define F_INF __int_as_float(0x7f800000)

// ---------------------------------------------------------------------------
// Single fused kernel. One block per row b, 1024 threads. grid=128 <= #SMs,
// so all blocks are co-resident (flag-based completion is deadlock-free).
//   Phase 1: sign-only scan of u = target/amp via float4 loads -> shift
//   Phase 2: gather K=100 circularly shifted X / dvals into shared
//   Phase 3: stable rank-sort (8 threads/element), packed {x,d,idx}
//   Phase 3b: 512-entry lower_bound LUT
//   Phase 4: bucket -> LUT -> short verify walk -> 2-candidate NN
//            (exact jnp.argmin first-index tie-break)
//   Phase 5: variance (ddof=0, points 1..P-1); float accum, double combine
//   Phase 6: blocks 1..127 publish loss via fence+flag; block 0 polls,
//            reduces the 128 losses, writes mean, resets flags.
// ---------------------------------------------------------------------------
__global__ void __launch_bounds__(T_, 1)
k_fused(const float* __restrict__ preds,
        const float* __restrict__ target,
        const float* __restrict__ Xffp,
        const float* __restrict__ amp,
        const float* __restrict__ pointx,
        float* __restrict__ out)
{
    const int b   = blockIdx.x;
    const int tid = threadIdx.x;          // 1024
    const int w   = tid >> 5, l = tid & 31;

    const float* t = target + (size_t)b * N_;
    const float* a = amp    + (size_t)b * N_;
    const float* p = preds  + (size_t)b * N_;
    const float* x = Xffp   + (size_t)b * N_;

    // Prefetch pointx early (independent of phases 1-3)
    float px[4];
    #pragma unroll
    for (int j = 0; j < 4; j++) px[j] = pointx[tid + j * T_];

    // ---- Phase 1: min index with u>=0, max index with u<=0 (sign-only) ----
    // Each thread owns 4 consecutive elements via one float4 per array.
    const float4 tv4 = ((const float4*)t)[tid];
    const float4 av4 = ((const float4*)a)[tid];
    int minGe = N_;
    int maxLe = -1;
    {
        const float tv[4] = {tv4.x, tv4.y, tv4.z, tv4.w};
        const float av[4] = {av4.x, av4.y, av4.z, av4.w};
        #pragma unroll
        for (int c = 3; c >= 0; c--) {       // descending: first match = min idx
            int  sgn = __float_as_int(tv[c]) ^ __float_as_int(av[c]);
            bool zer = (tv[c] == 0.0f);
            if (zer || sgn >= 0) minGe = tid * 4 + c;       // u >= 0
        }
        #pragma unroll
        for (int c = 0; c <= 3; c++) {       // ascending: last match = max idx
            int  sgn = __float_as_int(tv[c]) ^ __float_as_int(av[c]);
            bool zer = (tv[c] == 0.0f);
            if (zer || sgn < 0) maxLe = tid * 4 + c;        // u <= 0
        }
    }
    minGe = __reduce_min_sync(0xffffffffu, minGe);
    maxLe = __reduce_max_sync(0xffffffffu, maxLe);
    __shared__ int sMin[32], sMax[32];
    __shared__ int sShift;
    if (l == 0) { sMin[w] = minGe; sMax[w] = maxLe; }
    __syncthreads();
    if (w == 0) {
        int mg = __reduce_min_sync(0xffffffffu, sMin[l]);
        int ml = __reduce_max_sync(0xffffffffu, sMax[l]);
        if (l == 0) {
            int j_left  = (mg == N_) ? 0 : mg;             // jnp.argmax all-False -> 0
            int m_right = (ml < 0)   ? 0 : (N_ - 1 - ml);
            float first = t[0]      / a[0];                // L1/L2 hot
            float last  = t[N_ - 1] / a[N_ - 1];
            bool left_case = (last < 0.0f) && (first < 0.0f);
            sShift = left_case ? -(j_left + 1) : m_right;
        }
    }
    __syncthreads();

    // ---- Phase 2: gather K=100 shifted values ----
    __shared__ float sX[K_], sD[K_];
    if (tid < K_) {
        int src = (tid - sShift) % N_;
        if (src < 0) src += N_;
        float av = a[src];
        sX[tid] = x[src];
        sD[tid] = t[src] / av - p[src] / av;   // u - u_uifft (two divisions, as in ref)
    }
    __syncthreads();

    // ---- Phase 3: stable rank-sort, 8 threads per element ----
    __shared__ float  sXs[K_];
    __shared__ float4 sPk[K_];                 // {x, d, orig idx (bits), 0}
    {
        const int k = tid >> 3, part = tid & 7;
        if (k < K_) {
            float v = sX[k];
            int r = 0;
            for (int j = part; j < K_; j += 8) {
                float u = sX[j];
                r += (u < v) || (u == v && j < k);
            }
            r += __shfl_down_sync(0xffffffffu, r, 4, 8);
            r += __shfl_down_sync(0xffffffffu, r, 2, 8);
            r += __shfl_down_sync(0xffffffffu, r, 1, 8);
            if (part == 0) {
                sXs[r] = v;
                sPk[r] = make_float4(v, sD[k], __int_as_float(k), 0.f);
            }
        }
    }
    __syncthreads();

    // ---- Phase 3b: lower_bound LUT over NB_ uniform buckets ----
    __shared__ int sLUT[NB_];
    const float xmin = sXs[0];
    const float xmax = sXs[K_ - 1];
    if (tid < NB_) {
        float wB   = (xmax - xmin) * (1.0f / NB_);
        float edge = fmaf((float)tid, wB, xmin);
        int p0 = 0;
        #pragma unroll
        for (int step = 64; step >= 1; step >>= 1)
            if (p0 + step <= K_ && sXs[p0 + step - 1] < edge) p0 += step;
        sLUT[tid] = p0;                        // #values < edge
    }
    __syncthreads();

    // ---- Phase 4+5: LUT-guided NN + variance, 4 points/thread ----
    const float range = xmax - xmin;
    const float inv   = (range > 0.f) ? ((float)NB_ / range) : 0.f;

    float s = 0.f, s2 = 0.f;
    #pragma unroll
    for (int j = 0; j < 4; j++) {
        const int   pi = tid + j * T_;
        const float pv = px[j];
        int g = (int)((pv - xmin) * inv);
        g = min(max(g, 0), NB_ - 1);
        int pos = sLUT[g];
        // verify walk -> exact lower_bound (robust to bucket-edge rounding)
        while (pos < K_ && sXs[pos] < pv) ++pos;
        while (pos > 0 && sXs[pos - 1] >= pv) --pos;
        // two candidates: pos-1 (strictly < pv) and pos (>= pv)
        float dL = F_INF, vL = 0.f; int iL = 0x7fffffff;
        if (pos > 0) {
            float4 c = sPk[pos - 1];
            dL = fabsf(pv - c.x); vL = c.y; iL = __float_as_int(c.z);
        }
        float dR = F_INF, vR = 0.f; int iR = 0x7fffffff;
        if (pos < K_) {
            float4 c = sPk[pos];
            dR = fabsf(pv - c.x); vR = c.y; iR = __float_as_int(c.z);
        }
        bool takeL = (dL < dR) || (dL == dR && iL < iR);   // first-index tie-break
        float dv = takeL ? vL : vR;
        if (pi >= 1) {                         // diff[:, 1:] excludes point 0
            s  += dv;
            s2  = fmaf(dv, dv, s2);
        }
    }
    #pragma unroll
    for (int o = 16; o > 0; o >>= 1) {
        s  += __shfl_down_sync(0xffffffffu, s,  o);
        s2 += __shfl_down_sync(0xffffffffu, s2, o);
    }
    __shared__ float rs[32], rs2[32];
    if (l == 0) { rs[w] = s; rs2[w] = s2; }
    __syncthreads();
    if (w == 0) {
        double ds  = (double)rs [l];
        double ds2 = (double)rs2[l];
        #pragma unroll
        for (int o = 16; o > 0; o >>= 1) {
            ds  += __shfl_down_sync(0xffffffffu, ds,  o);
            ds2 += __shfl_down_sync(0xffffffffu, ds2, o);
        }
        if (l == 0) {
            const double M = (double)(P_ - 1);   // 4095, ddof=0
            double mean = ds / M;
            g_loss[b] = ds2 / M - mean * mean;
        }
    }
    __syncthreads();                            // g_loss[b] visible block-wide

    // ---- Phase 6: flag-based completion (no atomics) ----
    if (b != 0) {
        if (tid == 0) {
            __threadfence();                    // order g_loss[b] before flag
            *(volatile int*)&g_flag[b] = 1;
        }
        return;
    }
    // Block 0: poll the 127 flags (all blocks co-resident -> no deadlock)
    bool mydone;
    do {
        int f = 1;
        if (tid > 0 && tid < B_) f = *(volatile int*)&g_flag[tid];
        mydone = (f != 0);
    } while (!__syncthreads_and(mydone));
    __threadfence();                            // acquire: order loss reads

    double v = (tid < B_) ? g_loss[tid] : 0.0;
    #pragma unroll
    for (int o = 16; o > 0; o >>= 1) v += __shfl_down_sync(0xffffffffu, v, o);
    __shared__ double rr[4];
    if (w < 4 && l == 0) rr[w] = v;
    __syncthreads();
    if (tid == 0)
        out[0] = (float)((rr[0] + rr[1] + rr[2] + rr[3]) / (double)B_);
    if (tid > 0 && tid < B_)
        g_flag[tid] = 0;                        // reset for next graph replay
}

// ---------------------------------------------------------------------------
// Inputs (metadata order): preds, target, Xffp, dXffp_Amp, pointx
// Output: scalar float32
// ---------------------------------------------------------------------------
extern "C" void kernel_launch(void* const* d_in, const int* in_sizes, int n_in,
                              void* d_out, int out_size)
{
    const float* preds  = (const float*)d_in[0];
    const float* target = (const float*)d_in[1];
    const float* Xffp   = (const float*)d_in[2];
    const float* amp    = (const float*)d_in[3];
    const float* pointx = (const float*)d_in[4];

    k_fused<<<B_, T_>>>(preds, target, Xffp, amp, pointx, (float*)d_out);
}

// round 8
// speedup vs baseline: 1.0415x; 1.0415x over previous
#include <cuda_runtime.h>

#define B_  128
#define N_  4096
#define K_  100
#define P_  4096
#define T_  1024          // threads per block

// Device globals (no allocation in kernel_launch, per harness rules)
__device__ double g_loss[B_];
__device__ int    g_flag[B_];    // zero-init; block 0 resets after consuming

#define F_INF __int_as_float(0x7f800000)

// ---------------------------------------------------------------------------
// Single fused kernel. One block per row b, 1024 threads. grid=128 <= #SMs,
// so all blocks are co-resident (flag-based completion is deadlock-free).
//   Phase 0: prefetch x/p rows into L1 (covers Phase 2's gather latency)
//   Phase 1: sign-only scan of u = target/amp via float4 -> shift
//            (first/last elements forwarded from registers, no reload)
//   Phase 2: gather K=100 circularly shifted X / dvals into shared (L1 hits)
//   Phase 3: stable rank-sort (8 threads/element), packed {x,d,idx} float4
//   Phase 4: per point branchless binary search + 2-candidate NN
//            (exact jnp.argmin first-index tie-break)
//   Phase 5: variance (ddof=0, points 1..P-1); float accum, double combine
//   Phase 6: blocks 1..127 publish loss via fence+flag; block 0 polls,
//            reduces the 128 losses, writes mean, resets flags.
// ---------------------------------------------------------------------------
__global__ void __launch_bounds__(T_, 1)
k_fused(const float* __restrict__ preds,
        const float* __restrict__ target,
        const float* __restrict__ Xffp,
        const float* __restrict__ amp,
        const float* __restrict__ pointx,
        float* __restrict__ out)
{
    const int b   = blockIdx.x;
    const int tid = threadIdx.x;          // 1024
    const int w   = tid >> 5, l = tid & 31;

    const float* t = target + (size_t)b * N_;
    const float* a = amp    + (size_t)b * N_;
    const float* p = preds  + (size_t)b * N_;
    const float* x = Xffp   + (size_t)b * N_;

    // ---- Phase 0: prefetch x/p rows into L1 (128 lines of 128B each) ----
    if (tid < 128)
        asm volatile("prefetch.global.L1 [%0];" :: "l"(x + tid * 32));
    else if (tid < 256)
        asm volatile("prefetch.global.L1 [%0];" :: "l"(p + (tid - 128) * 32));

    // Prefetch pointx early (independent of phases 1-3)
    float px[4];
    #pragma unroll
    for (int j = 0; j < 4; j++) px[j] = pointx[tid + j * T_];

    // ---- Phase 1: min index with u>=0, max index with u<=0 (sign-only) ----
    const float4 tv4 = ((const float4*)t)[tid];
    const float4 av4 = ((const float4*)a)[tid];
    int minGe = N_;
    int maxLe = -1;
    {
        const float tv[4] = {tv4.x, tv4.y, tv4.z, tv4.w};
        const float av[4] = {av4.x, av4.y, av4.z, av4.w};
        #pragma unroll
        for (int c = 3; c >= 0; c--) {       // descending: first match = min idx
            int  sgn = __float_as_int(tv[c]) ^ __float_as_int(av[c]);
            bool zer = (tv[c] == 0.0f);
            if (zer || sgn >= 0) minGe = tid * 4 + c;       // u >= 0
        }
        #pragma unroll
        for (int c = 0; c <= 3; c++) {       // ascending: last match = max idx
            int  sgn = __float_as_int(tv[c]) ^ __float_as_int(av[c]);
            bool zer = (tv[c] == 0.0f);
            if (zer || sgn < 0) maxLe = tid * 4 + c;        // u <= 0
        }
    }
    minGe = __reduce_min_sync(0xffffffffu, minGe);
    maxLe = __reduce_max_sync(0xffffffffu, maxLe);
    __shared__ int   sMin[32], sMax[32];
    __shared__ float sFL[4];                 // t0, a0, tN, aN from registers
    __shared__ int   sShift;
    if (l == 0) { sMin[w] = minGe; sMax[w] = maxLe; }
    if (tid == 0)      { sFL[0] = tv4.x; sFL[1] = av4.x; }
    if (tid == T_ - 1) { sFL[2] = tv4.w; sFL[3] = av4.w; }   // t[4095], a[4095]
    __syncthreads();
    if (w == 0) {
        int mg = __reduce_min_sync(0xffffffffu, sMin[l]);
        int ml = __reduce_max_sync(0xffffffffu, sMax[l]);
        if (l == 0) {
            int j_left  = (mg == N_) ? 0 : mg;             // jnp.argmax all-False -> 0
            int m_right = (ml < 0)   ? 0 : (N_ - 1 - ml);
            float first = sFL[0] / sFL[1];
            float last  = sFL[2] / sFL[3];
            bool left_case = (last < 0.0f) && (first < 0.0f);
            sShift = left_case ? -(j_left + 1) : m_right;
        }
    }
    __syncthreads();

    // ---- Phase 2: gather K=100 shifted values (x/p now L1-resident) ----
    __shared__ float sX[K_], sD[K_];
    if (tid < K_) {
        int src = (tid - sShift) % N_;
        if (src < 0) src += N_;
        float av = a[src];
        sX[tid] = x[src];
        sD[tid] = t[src] / av - p[src] / av;   // u - u_uifft (two divisions, as in ref)
    }
    __syncthreads();

    // ---- Phase 3: stable rank-sort, 8 threads per element ----
    __shared__ float  sXs[K_];
    __shared__ float4 sPk[K_];                 // {x, d, orig idx (bits), 0}
    {
        const int k = tid >> 3, part = tid & 7;
        if (k < K_) {
            float v = sX[k];
            int r = 0;
            for (int j = part; j < K_; j += 8) {
                float u = sX[j];
                r += (u < v) || (u == v && j < k);
            }
            r += __shfl_down_sync(0xffffffffu, r, 4, 8);
            r += __shfl_down_sync(0xffffffffu, r, 2, 8);
            r += __shfl_down_sync(0xffffffffu, r, 1, 8);
            if (part == 0) {
                sXs[r] = v;
                sPk[r] = make_float4(v, sD[k], __int_as_float(k), 0.f);
            }
        }
    }
    __syncthreads();

    // ---- Phase 4+5: binary-search NN + variance, 4 points/thread ----
    float s = 0.f, s2 = 0.f;
    #pragma unroll
    for (int j = 0; j < 4; j++) {
        const int   pi = tid + j * T_;
        const float pv = px[j];
        // branchless lower_bound: pos = #elements < pv
        int pos = 0;
        #pragma unroll
        for (int step = 64; step >= 1; step >>= 1)
            if (pos + step <= K_ && sXs[pos + step - 1] < pv) pos += step;
        // two candidates: pos-1 (strictly < pv) and pos (>= pv)
        float dL = F_INF, vL = 0.f; int iL = 0x7fffffff;
        if (pos > 0) {
            float4 c = sPk[pos - 1];
            dL = fabsf(pv - c.x); vL = c.y; iL = __float_as_int(c.z);
        }
        float dR = F_INF, vR = 0.f; int iR = 0x7fffffff;
        if (pos < K_) {
            float4 c = sPk[pos];
            dR = fabsf(pv - c.x); vR = c.y; iR = __float_as_int(c.z);
        }
        bool takeL = (dL < dR) || (dL == dR && iL < iR);   // first-index tie-break
        float dv = takeL ? vL : vR;
        if (pi >= 1) {                         // diff[:, 1:] excludes point 0
            s  += dv;
            s2  = fmaf(dv, dv, s2);
        }
    }
    #pragma unroll
    for (int o = 16; o > 0; o >>= 1) {
        s  += __shfl_down_sync(0xffffffffu, s,  o);
        s2 += __shfl_down_sync(0xffffffffu, s2, o);
    }
    __shared__ float rs[32], rs2[32];
    if (l == 0) { rs[w] = s; rs2[w] = s2; }
    __syncthreads();
    if (w == 0) {
        double ds  = (double)rs [l];
        double ds2 = (double)rs2[l];
        #pragma unroll
        for (int o = 16; o > 0; o >>= 1) {
            ds  += __shfl_down_sync(0xffffffffu, ds,  o);
            ds2 += __shfl_down_sync(0xffffffffu, ds2, o);
        }
        if (l == 0) {
            const double M = (double)(P_ - 1);   // 4095, ddof=0
            double mean = ds / M;
            g_loss[b] = ds2 / M - mean * mean;
        }
    }

    // ---- Phase 6: flag-based completion (no atomics) ----
    if (b != 0) {
        if (w == 0 && l == 0) {
            __threadfence();                    // order g_loss[b] before flag
            *(volatile int*)&g_flag[b] = 1;
        }
        return;
    }
    // Block 0: poll the 127 flags (all blocks co-resident -> no deadlock).
    // The first __syncthreads_and also orders warp 0's g_loss[0] write for
    // the block-0 readers below.
    bool mydone;
    do {
        int f = 1;
        if (tid > 0 && tid < B_) f = *(volatile int*)&g_flag[tid];
        mydone = (f != 0);
    } while (!__syncthreads_and(mydone));
    __threadfence();                            // acquire: order loss reads

    double v = (tid < B_) ? g_loss[tid] : 0.0;
    #pragma unroll
    for (int o = 16; o > 0; o >>= 1) v += __shfl_down_sync(0xffffffffu, v, o);
    __shared__ double rr[4];
    if (w < 4 && l == 0) rr[w] = v;
    __syncthreads();
    if (tid == 0)
        out[0] = (float)((rr[0] + rr[1] + rr[2] + rr[3]) / (double)B_);
    if (tid > 0 && tid < B_)
        g_flag[tid] = 0;                        // reset for next graph replay
}

// ---------------------------------------------------------------------------
// Inputs (metadata order): preds, target, Xffp, dXffp_Amp, pointx
// Output: scalar float32
// ---------------------------------------------------------------------------
extern "C" void kernel_launch(void* const* d_in, const int* in_sizes, int n_in,
                              void* d_out, int out_size)
{
    const float* preds  = (const float*)d_in[0];
    const float* target = (const float*)d_in[1];
    const float* Xffp   = (const float*)d_in[2];
    const float* amp    = (const float*)d_in[3];
    const float* pointx = (const float*)d_in[4];

    k_fused<<<B_, T_>>>(preds, target, Xffp, amp, pointx, (float*)d_out);
}